// round 1
// baseline (speedup 1.0000x reference)
#include <cuda_runtime.h>

#define B_  2048
#define E_  32
#define N_  32
#define D_  64
#define BE_ (B_*E_)

// One warp processes one (b,e) pair end-to-end:
//   scores -> softmax -> weighted mean of neighbors -> +self -> x@W^T+b -> relu
__global__ __launch_bounds__(256)
void sum_aggregator_kernel(const float* __restrict__ selfv,   // [B,E,D]
                           const float* __restrict__ nbv,     // [B,E,N,D]
                           const float* __restrict__ relv,    // [B,E,N,D]
                           const float* __restrict__ userv,   // [B,D]
                           const float* __restrict__ W,       // [D,D] row-major
                           const float* __restrict__ bl,      // [D]
                           float* __restrict__ out,           // [B,E,D]
                           int total_warps)
{
    // Interleaved W tile in smem:
    // Wq[k][l] = ( W[2l][2k], W[2l][2k+1], W[2l+1][2k], W[2l+1][2k+1] )
    // so lane l (outputs j=2l,2l+1) fetches one float4 per k-step, conflict-free.
    __shared__ float4 Wq[32][32];

    const int tid  = threadIdx.x;
    const int lane = tid & 31;
    const int wid  = tid >> 5;

    for (int i = tid; i < 32 * 32; i += 256) {
        int k = i >> 5, l = i & 31;
        Wq[k][l] = make_float4(W[(2*l  )*D_ + 2*k], W[(2*l  )*D_ + 2*k + 1],
                               W[(2*l+1)*D_ + 2*k], W[(2*l+1)*D_ + 2*k + 1]);
    }
    __syncthreads();

    const float2 bb = *reinterpret_cast<const float2*>(bl + 2*lane);

    int gwarp = blockIdx.x * 8 + wid;
    for (int pair = gwarp; pair < BE_; pair += total_warps) {
        const int b = pair >> 5;  // / E_
        const float2 u = *reinterpret_cast<const float2*>(userv + (size_t)b*D_ + 2*lane);

        // ---- Pass 1: scores[n] = dot(user, rel[n,:]) / D ----
        const float* relp = relv + (size_t)pair * (N_*D_);
        float v[N_];
        #pragma unroll
        for (int n = 0; n < N_; n++) {
            float2 r = *reinterpret_cast<const float2*>(relp + n*D_ + 2*lane);
            v[n] = u.x * r.x + u.y * r.y;
        }

        // Reduce-scatter across the warp: lane n ends up owning score[n].
        #pragma unroll
        for (int off = 16; off >= 1; off >>= 1) {
            const bool up = (lane & off) != 0;
            #pragma unroll
            for (int k = 0; k < off; k++) {
                float mine = up ? v[off + k] : v[k];
                float oth  = up ? v[k]       : v[off + k];
                v[k] = mine + __shfl_xor_sync(0xffffffffu, oth, off);
            }
        }
        float s = v[0] * (1.0f / (float)D_);

        // ---- Softmax over n (value-per-lane) ----
        float m = s;
        #pragma unroll
        for (int off = 16; off >= 1; off >>= 1)
            m = fmaxf(m, __shfl_xor_sync(0xffffffffu, m, off));
        float e = __expf(s - m);
        float sum = e;
        #pragma unroll
        for (int off = 16; off >= 1; off >>= 1)
            sum += __shfl_xor_sync(0xffffffffu, sum, off);
        // fold the mean-over-N (1/32) into the attention weight
        const float a = e / (sum * (float)N_);

        // ---- Pass 2: agg = sum_n a[n] * nb[n,:] ----
        const float* nbp = nbv + (size_t)pair * (N_*D_);
        float2 acc = make_float2(0.f, 0.f);
        #pragma unroll
        for (int n = 0; n < N_; n++) {
            float an = __shfl_sync(0xffffffffu, a, n);
            float2 x = *reinterpret_cast<const float2*>(nbp + n*D_ + 2*lane);
            acc.x = fmaf(an, x.x, acc.x);
            acc.y = fmaf(an, x.y, acc.y);
        }

        float2 sv = *reinterpret_cast<const float2*>(selfv + (size_t)pair*D_ + 2*lane);
        float2 o  = make_float2(sv.x + acc.x, sv.y + acc.y);

        // ---- Linear: y[j] = sum_d o[d] * W[j][d] + b[j], then relu ----
        float y0 = bb.x, y1 = bb.y;
        #pragma unroll
        for (int k = 0; k < 32; k++) {
            float ox = __shfl_sync(0xffffffffu, o.x, k);   // o[2k]
            float oy = __shfl_sync(0xffffffffu, o.y, k);   // o[2k+1]
            float4 w = Wq[k][lane];
            y0 = fmaf(ox, w.x, fmaf(oy, w.y, y0));
            y1 = fmaf(ox, w.z, fmaf(oy, w.w, y1));
        }

        float2 res = make_float2(fmaxf(y0, 0.f), fmaxf(y1, 0.f));
        *reinterpret_cast<float2*>(out + (size_t)pair*D_ + 2*lane) = res;
    }
}

extern "C" void kernel_launch(void* const* d_in, const int* in_sizes, int n_in,
                              void* d_out, int out_size)
{
    const float* selfv = (const float*)d_in[0];  // self_vectors      [B,E,D]
    const float* nbv   = (const float*)d_in[1];  // neighbor_vectors  [B,E,N,D]
    const float* relv  = (const float*)d_in[2];  // neighbor_relations[B,E,N,D]
    const float* userv = (const float*)d_in[3];  // user_embeddings   [B,D]
    // d_in[4] = masks (unused by the module)
    const float* W     = (const float*)d_in[5];  // [D,D]
    const float* bl    = (const float*)d_in[6];  // [D]
    float* out = (float*)d_out;

    // Size the grid to exactly the resident capacity (one logical wave,
    // grid-stride loop distributes 65536 pairs evenly +/-1).
    int dev = 0, sms = 148, occ = 0;
    cudaGetDevice(&dev);
    cudaDeviceGetAttribute(&sms, cudaDevAttrMultiProcessorCount, dev);
    cudaOccupancyMaxActiveBlocksPerMultiprocessor(&occ, sum_aggregator_kernel, 256, 0);
    if (occ < 1) occ = 1;
    int blocks = occ * sms;
    int max_blocks = BE_ / 8;            // never more warps than pairs
    if (blocks > max_blocks) blocks = max_blocks;
    int total_warps = blocks * 8;

    sum_aggregator_kernel<<<blocks, 256>>>(selfv, nbv, relv, userv, W, bl, out,
                                           total_warps);
}